// round 16
// baseline (speedup 1.0000x reference)
#include <cuda_runtime.h>
#include <cuda_bf16.h>
#include <cstdint>

// B=8, C=16, L=512, D=256.  M = B*L*C = 65536 rows of xf (row m = (b*512+l)*16 + c)
#define M_ROWS 65536
#define DMODEL 256
#define KPHYS  512      // physical [hi|lo]; logical bf16x3 K=768 via chunk remap
#define NKCHUNK 24      // logical k-chunks of 32
#define LDS    40       // padded smem row (bf16 elems) = 80 bytes
#define NSTAGE 3

// ---------------- device scratch (allocation-free rule) ---------------------
__device__ float g_qk[(size_t)M_ROWS * 512];              // q | k, fp32
__device__ float g_a[M_ROWS];                             // diag softmax scale
__device__ __nv_bfloat16 g_xcat[(size_t)M_ROWS * KPHYS];  // X as [hi|lo]
__device__ __nv_bfloat16 g_wqk[(size_t)512 * KPHYS];      // Wq,Wk as [hi|lo]
__device__ __nv_bfloat16 g_wc[(size_t)DMODEL * KPHYS];    // (Wout@Wv) as [hi|lo]
__device__ float g_bc[DMODEL];                            // Wout@bv

__device__ __forceinline__ size_t xrow_base(int m) {
    int p = m >> 4;          // position = b*512 + l
    int c = m & 15;
    int b = p >> 9;
    int l = p & 511;
    return ((size_t)((b << 13) + (c << 9) + l)) << 8;
}

__device__ __forceinline__ void split2(float v, __nv_bfloat16* h, __nv_bfloat16* l) {
    *h = __float2bfloat16(v);
    *l = __float2bfloat16(v - __bfloat162float(*h));
}

// tanh via hw ex2/rcp approx: err ~1e-6, tails exact (+inf->1, -inf->-1)
__device__ __forceinline__ float fast_tanh(float x) {
    float e, r;
    float t = x * 2.8853900817779268f;      // 2*log2(e)*x
    asm("ex2.approx.f32 %0, %1;" : "=f"(e) : "f"(t));
    asm("rcp.approx.f32 %0, %1;" : "=f"(r) : "f"(e + 1.0f));
    return fmaf(-2.0f, r, 1.0f);
}

// ---------------- conversions: [hi|lo] ----------------------------------
__global__ void convert_x_kernel(const float* __restrict__ x)
{
    int t = blockIdx.x * 256 + threadIdx.x;   // 65536*64 threads
    int m = t >> 6;
    int d = (t & 63) << 2;
    float4 v = *(const float4*)(x + xrow_base(m) + d);
    __nv_bfloat16 h[4], l[4];
    split2(v.x, &h[0], &l[0]); split2(v.y, &h[1], &l[1]);
    split2(v.z, &h[2], &l[2]); split2(v.w, &h[3], &l[3]);
    size_t base = (size_t)m * KPHYS + d;
    *(uint2*)&g_xcat[base]       = *(uint2*)h;
    *(uint2*)&g_xcat[base + 256] = *(uint2*)l;
}

__global__ void convert_wqk_kernel(const float* __restrict__ Wqkv)
{
    int t = blockIdx.x * 256 + threadIdx.x;   // 512*64 threads
    int n = t >> 6;
    int d = (t & 63) << 2;
    float4 v = *(const float4*)(Wqkv + (size_t)n * DMODEL + d);
    __nv_bfloat16 h[4], l[4];
    split2(v.x, &h[0], &l[0]); split2(v.y, &h[1], &l[1]);
    split2(v.z, &h[2], &l[2]); split2(v.w, &h[3], &l[3]);
    size_t base = (size_t)n * KPHYS + d;
    *(uint2*)&g_wqk[base]       = *(uint2*)h;
    *(uint2*)&g_wqk[base + 256] = *(uint2*)l;
}

__global__ void fuse_w_kernel(const float* __restrict__ Wqkv,
                              const float* __restrict__ bqkv,
                              const float* __restrict__ Wout)
{
    __shared__ float wrow[DMODEL];
    int n = blockIdx.x;
    int k = threadIdx.x;
    wrow[k] = Wout[n * DMODEL + k];
    __syncthreads();
    float s = 0.f;
    #pragma unroll 8
    for (int j = 0; j < DMODEL; j++)
        s = fmaf(wrow[j], Wqkv[(size_t)(512 + j) * DMODEL + k], s);
    __nv_bfloat16 h, l;
    split2(s, &h, &l);
    size_t base = (size_t)n * KPHYS + k;
    g_wc[base]       = h;
    g_wc[base + 256] = l;
    if (k == 0) {
        float t = 0.f;
        for (int j = 0; j < DMODEL; j++)
            t = fmaf(wrow[j], bqkv[512 + j], t);
        g_bc[n] = t;
    }
}

// ---------------- bf16 MMA GEMM: 128x128 tile, 3-stage pipeline -------------
__device__ __forceinline__ void cp16(uint32_t dst, const void* src) {
    asm volatile("cp.async.cg.shared.global [%0], [%1], 16;\n" :: "r"(dst), "l"(src));
}

__device__ __forceinline__ void mma16816(float* d, const uint32_t* a,
                                         uint32_t b0, uint32_t b1) {
    asm volatile(
        "mma.sync.aligned.m16n8k16.row.col.f32.bf16.bf16.f32 "
        "{%0,%1,%2,%3}, {%4,%5,%6,%7}, {%8,%9}, {%0,%1,%2,%3};\n"
        : "+f"(d[0]), "+f"(d[1]), "+f"(d[2]), "+f"(d[3])
        : "r"(a[0]), "r"(a[1]), "r"(a[2]), "r"(a[3]), "r"(b0), "r"(b1));
}

// logical chunk -> physical chunk:  A=[hi|lo|hi], B=[hi|hi|lo]
__device__ __forceinline__ int aphys(int kc) { return kc < 16 ? kc : kc - 16; }
__device__ __forceinline__ int bphys(int kc) { return kc < 8  ? kc : kc - 8;  }

// qk mode (false): g_qk[m*512+n] = x@Wqkv[0:512]^T + bqkv       (N=512)
// out mode (true): out[xbase(m)+n] = a[m]*(x@Wc^T + bc) + bout  (N=256)
template<bool OUT_MODE>
__global__ __launch_bounds__(256, 2)
void mma_gemm(const float* __restrict__ biasIn,
              const float* __restrict__ boutv,
              float* __restrict__ OutP)
{
    __shared__ __nv_bfloat16 As[NSTAGE][128 * LDS];
    __shared__ __nv_bfloat16 Bs[NSTAGE][128 * LDS];

    const __nv_bfloat16* Bg = OUT_MODE ? g_wc : g_wqk;
    const float* bias = OUT_MODE ? g_bc : biasIn;

    const int tid  = threadIdx.x;
    const int bm   = blockIdx.y, bn = blockIdx.x;
    const int lane = tid & 31;
    const int w    = tid >> 5;
    const int wm   = w >> 1;          // 0..3 (32 rows each)
    const int wn   = w & 1;           // 0..1 (64 cols each)

    const int row_l = tid >> 1;       // 0..127
    const int ch0   = (tid & 1) * 2;  // 0 or 2

    const __nv_bfloat16* agp = g_xcat + (size_t)(bm * 128 + row_l) * KPHYS + ch0 * 8;
    const __nv_bfloat16* bgp = Bg     + (size_t)(bn * 128 + row_l) * KPHYS + ch0 * 8;
    const uint32_t asb = (uint32_t)__cvta_generic_to_shared(&As[0][0]);
    const uint32_t bsb = (uint32_t)__cvta_generic_to_shared(&Bs[0][0]);
    const uint32_t stageB = 128 * LDS * 2;           // 10240 bytes
    const uint32_t adst = asb + row_l * 80 + ch0 * 16;
    const uint32_t bdst = bsb + row_l * 80 + ch0 * 16;

    float acc[2][8][4];
    #pragma unroll
    for (int i = 0; i < 2; i++)
        #pragma unroll
        for (int j = 0; j < 8; j++)
            #pragma unroll
            for (int q = 0; q < 4; q++) acc[i][j][q] = 0.f;

    // prologue: stages 0,1 <- logical chunks 0,1 (phys == logical for 0,1)
    #pragma unroll
    for (int s = 0; s < 2; s++) {
        cp16(adst + s * stageB,      agp + s * 32);
        cp16(adst + s * stageB + 16, agp + s * 32 + 8);
        cp16(bdst + s * stageB,      bgp + s * 32);
        cp16(bdst + s * stageB + 16, bgp + s * 32 + 8);
        asm volatile("cp.async.commit_group;\n");
    }

    #pragma unroll 1
    for (int kc = 0; kc < NKCHUNK; kc++) {
        if (kc < NKCHUNK - 1)
            asm volatile("cp.async.wait_group 1;\n");
        else
            asm volatile("cp.async.wait_group 0;\n");
        __syncthreads();

        const int s = kc % NSTAGE;
        const uint32_t aB = asb + s * stageB;
        const uint32_t bB = bsb + s * stageB;

        #pragma unroll
        for (int ks = 0; ks < 2; ks++) {            // two k16 steps
            uint32_t a[2][4];
            #pragma unroll
            for (int mt = 0; mt < 2; mt++) {
                uint32_t addr = aB + (wm * 32 + mt * 16 + (lane & 15)) * 80
                              + ks * 32 + (lane >> 4) * 16;
                asm volatile("ldmatrix.sync.aligned.m8n8.x4.shared.b16 {%0,%1,%2,%3}, [%4];\n"
                    : "=r"(a[mt][0]), "=r"(a[mt][1]), "=r"(a[mt][2]), "=r"(a[mt][3])
                    : "r"(addr));
            }
            #pragma unroll
            for (int nt = 0; nt < 4; nt++) {        // each covers n16
                uint32_t b[4];
                uint32_t addr = bB + (wn * 64 + nt * 16 + ((lane >> 4) << 3) + (lane & 7)) * 80
                              + ks * 32 + ((lane >> 3) & 1) * 16;
                asm volatile("ldmatrix.sync.aligned.m8n8.x4.shared.b16 {%0,%1,%2,%3}, [%4];\n"
                    : "=r"(b[0]), "=r"(b[1]), "=r"(b[2]), "=r"(b[3])
                    : "r"(addr));
                #pragma unroll
                for (int mt = 0; mt < 2; mt++) {
                    mma16816(acc[mt][nt * 2],     a[mt], b[0], b[1]);
                    mma16816(acc[mt][nt * 2 + 1], a[mt], b[2], b[3]);
                }
            }
        }

        // issue loads for chunk kc+2 into stage (kc+2)%3 == (kc-1)%3.
        // The barrier at this iteration's top guarantees every warp finished
        // computing stage (kc-1)%3 (done in its previous iteration), so safe.
        if (kc + 2 < NKCHUNK) {
            const int kn = kc + 2;
            const int sn = kn % NSTAGE;
            const __nv_bfloat16* ag = agp + aphys(kn) * 32;
            const __nv_bfloat16* bg = bgp + bphys(kn) * 32;
            uint32_t ad = adst + sn * stageB;
            uint32_t bd = bdst + sn * stageB;
            cp16(ad,      ag);     cp16(ad + 16, ag + 8);
            cp16(bd,      bg);     cp16(bd + 16, bg + 8);
            asm volatile("cp.async.commit_group;\n");
        }
    }

    // epilogue
    const int qr = lane >> 2;
    const int qc = (lane & 3) * 2;
    #pragma unroll
    for (int mt = 0; mt < 2; mt++) {
        int mrow0 = bm * 128 + wm * 32 + mt * 16 + qr;
        int mrow1 = mrow0 + 8;
        if (!OUT_MODE) {
            #pragma unroll
            for (int nt = 0; nt < 8; nt++) {
                int col = bn * 128 + wn * 64 + nt * 8 + qc;
                float bx = bias[col], by = bias[col + 1];
                float2 v0 = { acc[mt][nt][0] + bx, acc[mt][nt][1] + by };
                float2 v1 = { acc[mt][nt][2] + bx, acc[mt][nt][3] + by };
                *(float2*)&g_qk[(size_t)mrow0 * 512 + col] = v0;
                *(float2*)&g_qk[(size_t)mrow1 * 512 + col] = v1;
            }
        } else {
            float a0 = g_a[mrow0], a1 = g_a[mrow1];
            size_t ob0 = xrow_base(mrow0), ob1 = xrow_base(mrow1);
            #pragma unroll
            for (int nt = 0; nt < 8; nt++) {
                int col = bn * 128 + wn * 64 + nt * 8 + qc;
                float bx = bias[col], by = bias[col + 1];
                float ox = boutv[col], oy = boutv[col + 1];
                float2 v0 = { fmaf(a0, acc[mt][nt][0] + bx, ox),
                              fmaf(a0, acc[mt][nt][1] + by, oy) };
                float2 v1 = { fmaf(a1, acc[mt][nt][2] + bx, ox),
                              fmaf(a1, acc[mt][nt][3] + by, oy) };
                *(float2*)&OutP[ob0 + col] = v0;
                *(float2*)&OutP[ob1 + col] = v1;
            }
        }
    }
}

// ---------------- K2: additive-attention diagonal softmax -------------------
__global__ __launch_bounds__(256)
void attn_kernel(const float* __restrict__ Vw, const float* __restrict__ bh)
{
    __shared__ float qs[16][256];
    __shared__ float ks[256][17];
    __shared__ float vws[256];

    int p = blockIdx.x;
    int tid = threadIdx.x;
    const size_t rowbase = (size_t)p * 16 * 512;

    #pragma unroll
    for (int it = 0; it < 4; it++) {
        int idx = tid + it * 256;
        int i = idx >> 6;
        int d = (idx & 63) << 2;
        float4 q  = *(const float4*)&g_qk[rowbase + (size_t)i * 512 + d];
        float4 kv = *(const float4*)&g_qk[rowbase + (size_t)i * 512 + 256 + d];
        qs[i][d + 0] = q.x + bh[d + 0];
        qs[i][d + 1] = q.y + bh[d + 1];
        qs[i][d + 2] = q.z + bh[d + 2];
        qs[i][d + 3] = q.w + bh[d + 3];
        ks[d + 0][i] = kv.x;
        ks[d + 1][i] = kv.y;
        ks[d + 2][i] = kv.z;
        ks[d + 3][i] = kv.w;
    }
    vws[tid] = Vw[tid];
    __syncthreads();

    int i = tid >> 4;
    int j = tid & 15;
    float s = 0.f;
    #pragma unroll 8
    for (int d = 0; d < DMODEL; d++)
        s = fmaf(vws[d], fast_tanh(qs[i][d] + ks[d][j]), s);

    float mx = s;
    #pragma unroll
    for (int off = 8; off > 0; off >>= 1)
        mx = fmaxf(mx, __shfl_xor_sync(0xffffffffu, mx, off));
    float e = expf(s - mx);
    float sum = e;
    #pragma unroll
    for (int off = 8; off > 0; off >>= 1)
        sum += __shfl_xor_sync(0xffffffffu, sum, off);

    if (j == i)
        g_a[(p << 4) + i] = e / sum;
}

// ---------------- launch -----------------------------------------------------
extern "C" void kernel_launch(void* const* d_in, const int* in_sizes, int n_in,
                              void* d_out, int out_size)
{
    const float* x    = (const float*)d_in[0];
    const float* Wqkv = (const float*)d_in[1];
    const float* bqkv = (const float*)d_in[2];
    const float* Vw   = (const float*)d_in[3];
    // d_in[4]=Vb, d_in[6]=ba cancel in softmax
    const float* bh   = (const float*)d_in[5];
    const float* Wout = (const float*)d_in[7];
    const float* bout = (const float*)d_in[8];
    float* out = (float*)d_out;

    convert_x_kernel<<<16384, 256>>>(x);
    convert_wqk_kernel<<<128, 256>>>(Wqkv);
    fuse_w_kernel<<<256, 256>>>(Wqkv, bqkv, Wout);
    mma_gemm<false><<<dim3(4, 512), 256>>>(bqkv, nullptr, nullptr);
    attn_kernel<<<4096, 256>>>(Vw, bh);
    mma_gemm<true><<<dim3(2, 512), 256>>>(nullptr, bout, out);
}

// round 17
// speedup vs baseline: 1.0022x; 1.0022x over previous
#include <cuda_runtime.h>
#include <cuda_bf16.h>
#include <cstdint>

// B=8, C=16, L=512, D=256.  M = B*L*C = 65536 rows of xf (row m = (b*512+l)*16 + c)
#define M_ROWS 65536
#define DMODEL 256
#define KPHYS  512      // physical [hi|lo]; logical bf16x3 K=768 via chunk remap
#define NKCHUNK 24      // logical k-chunks of 32
#define LDS    40       // padded smem row (bf16 elems) = 80 bytes
#define NSTAGE 3

// ---------------- device scratch (allocation-free rule) ---------------------
__device__ float g_qk[(size_t)M_ROWS * 512];              // q | k, fp32
__device__ float g_a[M_ROWS];                             // diag softmax scale
__device__ __nv_bfloat16 g_xcat[(size_t)M_ROWS * KPHYS];  // X as [hi|lo]
__device__ __nv_bfloat16 g_wqk[(size_t)512 * KPHYS];      // Wq,Wk as [hi|lo]
__device__ __nv_bfloat16 g_wc[(size_t)DMODEL * KPHYS];    // (Wout@Wv) as [hi|lo]
__device__ float g_bc[DMODEL];                            // Wout@bv

__device__ __forceinline__ size_t xrow_base(int m) {
    int p = m >> 4;          // position = b*512 + l
    int c = m & 15;
    int b = p >> 9;
    int l = p & 511;
    return ((size_t)((b << 13) + (c << 9) + l)) << 8;
}

__device__ __forceinline__ void split2(float v, __nv_bfloat16* h, __nv_bfloat16* l) {
    *h = __float2bfloat16(v);
    *l = __float2bfloat16(v - __bfloat162float(*h));
}

// tanh via hw ex2/rcp approx: err ~1e-6, tails exact (+inf->1, -inf->-1)
__device__ __forceinline__ float fast_tanh(float x) {
    float e, r;
    float t = x * 2.8853900817779268f;      // 2*log2(e)*x
    asm("ex2.approx.f32 %0, %1;" : "=f"(e) : "f"(t));
    asm("rcp.approx.f32 %0, %1;" : "=f"(r) : "f"(e + 1.0f));
    return fmaf(-2.0f, r, 1.0f);
}

// ---------------- conversions: [hi|lo] ----------------------------------
__global__ void convert_x_kernel(const float* __restrict__ x)
{
    int t = blockIdx.x * 256 + threadIdx.x;   // 65536*64 threads
    int m = t >> 6;
    int d = (t & 63) << 2;
    float4 v = *(const float4*)(x + xrow_base(m) + d);
    __nv_bfloat16 h[4], l[4];
    split2(v.x, &h[0], &l[0]); split2(v.y, &h[1], &l[1]);
    split2(v.z, &h[2], &l[2]); split2(v.w, &h[3], &l[3]);
    size_t base = (size_t)m * KPHYS + d;
    *(uint2*)&g_xcat[base]       = *(uint2*)h;
    *(uint2*)&g_xcat[base + 256] = *(uint2*)l;
}

__global__ void convert_wqk_kernel(const float* __restrict__ Wqkv)
{
    int t = blockIdx.x * 256 + threadIdx.x;   // 512*64 threads
    int n = t >> 6;
    int d = (t & 63) << 2;
    float4 v = *(const float4*)(Wqkv + (size_t)n * DMODEL + d);
    __nv_bfloat16 h[4], l[4];
    split2(v.x, &h[0], &l[0]); split2(v.y, &h[1], &l[1]);
    split2(v.z, &h[2], &l[2]); split2(v.w, &h[3], &l[3]);
    size_t base = (size_t)n * KPHYS + d;
    *(uint2*)&g_wqk[base]       = *(uint2*)h;
    *(uint2*)&g_wqk[base + 256] = *(uint2*)l;
}

__global__ void fuse_w_kernel(const float* __restrict__ Wqkv,
                              const float* __restrict__ bqkv,
                              const float* __restrict__ Wout)
{
    __shared__ float wrow[DMODEL];
    int n = blockIdx.x;
    int k = threadIdx.x;
    wrow[k] = Wout[n * DMODEL + k];
    __syncthreads();
    float s = 0.f;
    #pragma unroll 8
    for (int j = 0; j < DMODEL; j++)
        s = fmaf(wrow[j], Wqkv[(size_t)(512 + j) * DMODEL + k], s);
    __nv_bfloat16 h, l;
    split2(s, &h, &l);
    size_t base = (size_t)n * KPHYS + k;
    g_wc[base]       = h;
    g_wc[base + 256] = l;
    if (k == 0) {
        float t = 0.f;
        for (int j = 0; j < DMODEL; j++)
            t = fmaf(wrow[j], bqkv[512 + j], t);
        g_bc[n] = t;
    }
}

// ---------------- bf16 MMA GEMM: 128x128 tile, 3-stage pipeline -------------
__device__ __forceinline__ void cp16(uint32_t dst, const void* src) {
    asm volatile("cp.async.cg.shared.global [%0], [%1], 16;\n" :: "r"(dst), "l"(src));
}

__device__ __forceinline__ void mma16816(float* d, const uint32_t* a,
                                         uint32_t b0, uint32_t b1) {
    asm volatile(
        "mma.sync.aligned.m16n8k16.row.col.f32.bf16.bf16.f32 "
        "{%0,%1,%2,%3}, {%4,%5,%6,%7}, {%8,%9}, {%0,%1,%2,%3};\n"
        : "+f"(d[0]), "+f"(d[1]), "+f"(d[2]), "+f"(d[3])
        : "r"(a[0]), "r"(a[1]), "r"(a[2]), "r"(a[3]), "r"(b0), "r"(b1));
}

// logical chunk -> physical chunk:  A=[hi|lo|hi], B=[hi|hi|lo]
__device__ __forceinline__ int aphys(int kc) { return kc < 16 ? kc : kc - 16; }
__device__ __forceinline__ int bphys(int kc) { return kc < 8  ? kc : kc - 8;  }

// qk mode (false): g_qk[m*512+n] = x@Wqkv[0:512]^T + bqkv       (N=512)
// out mode (true): out[xbase(m)+n] = a[m]*(x@Wc^T + bc) + bout  (N=256)
template<bool OUT_MODE>
__global__ __launch_bounds__(256, 2)
void mma_gemm(const float* __restrict__ biasIn,
              const float* __restrict__ boutv,
              float* __restrict__ OutP)
{
    __shared__ __nv_bfloat16 As[NSTAGE][128 * LDS];
    __shared__ __nv_bfloat16 Bs[NSTAGE][128 * LDS];

    const __nv_bfloat16* Bg = OUT_MODE ? g_wc : g_wqk;
    const float* bias = OUT_MODE ? g_bc : biasIn;

    const int tid  = threadIdx.x;
    const int bm   = blockIdx.y, bn = blockIdx.x;
    const int lane = tid & 31;
    const int w    = tid >> 5;
    const int wm   = w >> 1;          // 0..3 (32 rows each)
    const int wn   = w & 1;           // 0..1 (64 cols each)

    const int row_l = tid >> 1;       // 0..127
    const int ch0   = (tid & 1) * 2;  // 0 or 2

    const __nv_bfloat16* agp = g_xcat + (size_t)(bm * 128 + row_l) * KPHYS + ch0 * 8;
    const __nv_bfloat16* bgp = Bg     + (size_t)(bn * 128 + row_l) * KPHYS + ch0 * 8;
    const uint32_t asb = (uint32_t)__cvta_generic_to_shared(&As[0][0]);
    const uint32_t bsb = (uint32_t)__cvta_generic_to_shared(&Bs[0][0]);
    const uint32_t stageB = 128 * LDS * 2;           // 10240 bytes
    const uint32_t adst = asb + row_l * 80 + ch0 * 16;
    const uint32_t bdst = bsb + row_l * 80 + ch0 * 16;

    float acc[2][8][4];
    #pragma unroll
    for (int i = 0; i < 2; i++)
        #pragma unroll
        for (int j = 0; j < 8; j++)
            #pragma unroll
            for (int q = 0; q < 4; q++) acc[i][j][q] = 0.f;

    // prologue: stages 0,1 <- logical chunks 0,1 (phys == logical for 0,1)
    #pragma unroll
    for (int s = 0; s < 2; s++) {
        cp16(adst + s * stageB,      agp + s * 32);
        cp16(adst + s * stageB + 16, agp + s * 32 + 8);
        cp16(bdst + s * stageB,      bgp + s * 32);
        cp16(bdst + s * stageB + 16, bgp + s * 32 + 8);
        asm volatile("cp.async.commit_group;\n");
    }

    #pragma unroll 1
    for (int kc = 0; kc < NKCHUNK; kc++) {
        if (kc < NKCHUNK - 1)
            asm volatile("cp.async.wait_group 1;\n");
        else
            asm volatile("cp.async.wait_group 0;\n");
        __syncthreads();

        const int s = kc % NSTAGE;
        const uint32_t aB = asb + s * stageB;
        const uint32_t bB = bsb + s * stageB;

        #pragma unroll
        for (int ks = 0; ks < 2; ks++) {            // two k16 steps
            uint32_t a[2][4];
            #pragma unroll
            for (int mt = 0; mt < 2; mt++) {
                uint32_t addr = aB + (wm * 32 + mt * 16 + (lane & 15)) * 80
                              + ks * 32 + (lane >> 4) * 16;
                asm volatile("ldmatrix.sync.aligned.m8n8.x4.shared.b16 {%0,%1,%2,%3}, [%4];\n"
                    : "=r"(a[mt][0]), "=r"(a[mt][1]), "=r"(a[mt][2]), "=r"(a[mt][3])
                    : "r"(addr));
            }
            #pragma unroll
            for (int nt = 0; nt < 4; nt++) {        // each covers n16
                uint32_t b[4];
                uint32_t addr = bB + (wn * 64 + nt * 16 + ((lane >> 4) << 3) + (lane & 7)) * 80
                              + ks * 32 + ((lane >> 3) & 1) * 16;
                asm volatile("ldmatrix.sync.aligned.m8n8.x4.shared.b16 {%0,%1,%2,%3}, [%4];\n"
                    : "=r"(b[0]), "=r"(b[1]), "=r"(b[2]), "=r"(b[3])
                    : "r"(addr));
                #pragma unroll
                for (int mt = 0; mt < 2; mt++) {
                    mma16816(acc[mt][nt * 2],     a[mt], b[0], b[1]);
                    mma16816(acc[mt][nt * 2 + 1], a[mt], b[2], b[3]);
                }
            }
        }

        // issue loads for chunk kc+2 into stage (kc+2)%3 == (kc-1)%3.
        // The barrier at this iteration's top guarantees every warp finished
        // computing stage (kc-1)%3 (done in its previous iteration), so safe.
        if (kc + 2 < NKCHUNK) {
            const int kn = kc + 2;
            const int sn = kn % NSTAGE;
            const __nv_bfloat16* ag = agp + aphys(kn) * 32;
            const __nv_bfloat16* bg = bgp + bphys(kn) * 32;
            uint32_t ad = adst + sn * stageB;
            uint32_t bd = bdst + sn * stageB;
            cp16(ad,      ag);     cp16(ad + 16, ag + 8);
            cp16(bd,      bg);     cp16(bd + 16, bg + 8);
            asm volatile("cp.async.commit_group;\n");
        }
    }

    // epilogue
    const int qr = lane >> 2;
    const int qc = (lane & 3) * 2;
    #pragma unroll
    for (int mt = 0; mt < 2; mt++) {
        int mrow0 = bm * 128 + wm * 32 + mt * 16 + qr;
        int mrow1 = mrow0 + 8;
        if (!OUT_MODE) {
            #pragma unroll
            for (int nt = 0; nt < 8; nt++) {
                int col = bn * 128 + wn * 64 + nt * 8 + qc;
                float bx = bias[col], by = bias[col + 1];
                float2 v0 = { acc[mt][nt][0] + bx, acc[mt][nt][1] + by };
                float2 v1 = { acc[mt][nt][2] + bx, acc[mt][nt][3] + by };
                *(float2*)&g_qk[(size_t)mrow0 * 512 + col] = v0;
                *(float2*)&g_qk[(size_t)mrow1 * 512 + col] = v1;
            }
        } else {
            float a0 = g_a[mrow0], a1 = g_a[mrow1];
            size_t ob0 = xrow_base(mrow0), ob1 = xrow_base(mrow1);
            #pragma unroll
            for (int nt = 0; nt < 8; nt++) {
                int col = bn * 128 + wn * 64 + nt * 8 + qc;
                float bx = bias[col], by = bias[col + 1];
                float ox = boutv[col], oy = boutv[col + 1];
                float2 v0 = { fmaf(a0, acc[mt][nt][0] + bx, ox),
                              fmaf(a0, acc[mt][nt][1] + by, oy) };
                float2 v1 = { fmaf(a1, acc[mt][nt][2] + bx, ox),
                              fmaf(a1, acc[mt][nt][3] + by, oy) };
                *(float2*)&OutP[ob0 + col] = v0;
                *(float2*)&OutP[ob1 + col] = v1;
            }
        }
    }
}

// ---------------- K2: additive-attention diagonal softmax -------------------
__global__ __launch_bounds__(256)
void attn_kernel(const float* __restrict__ Vw, const float* __restrict__ bh)
{
    __shared__ float qs[16][256];
    __shared__ float ks[256][17];
    __shared__ float vws[256];

    int p = blockIdx.x;
    int tid = threadIdx.x;
    const size_t rowbase = (size_t)p * 16 * 512;

    #pragma unroll
    for (int it = 0; it < 4; it++) {
        int idx = tid + it * 256;
        int i = idx >> 6;
        int d = (idx & 63) << 2;
        float4 q  = *(const float4*)&g_qk[rowbase + (size_t)i * 512 + d];
        float4 kv = *(const float4*)&g_qk[rowbase + (size_t)i * 512 + 256 + d];
        qs[i][d + 0] = q.x + bh[d + 0];
        qs[i][d + 1] = q.y + bh[d + 1];
        qs[i][d + 2] = q.z + bh[d + 2];
        qs[i][d + 3] = q.w + bh[d + 3];
        ks[d + 0][i] = kv.x;
        ks[d + 1][i] = kv.y;
        ks[d + 2][i] = kv.z;
        ks[d + 3][i] = kv.w;
    }
    vws[tid] = Vw[tid];
    __syncthreads();

    int i = tid >> 4;
    int j = tid & 15;
    float s = 0.f;
    #pragma unroll 8
    for (int d = 0; d < DMODEL; d++)
        s = fmaf(vws[d], fast_tanh(qs[i][d] + ks[d][j]), s);

    float mx = s;
    #pragma unroll
    for (int off = 8; off > 0; off >>= 1)
        mx = fmaxf(mx, __shfl_xor_sync(0xffffffffu, mx, off));
    float e = expf(s - mx);
    float sum = e;
    #pragma unroll
    for (int off = 8; off > 0; off >>= 1)
        sum += __shfl_xor_sync(0xffffffffu, sum, off);

    if (j == i)
        g_a[(p << 4) + i] = e / sum;
}

// ---------------- launch -----------------------------------------------------
extern "C" void kernel_launch(void* const* d_in, const int* in_sizes, int n_in,
                              void* d_out, int out_size)
{
    const float* x    = (const float*)d_in[0];
    const float* Wqkv = (const float*)d_in[1];
    const float* bqkv = (const float*)d_in[2];
    const float* Vw   = (const float*)d_in[3];
    // d_in[4]=Vb, d_in[6]=ba cancel in softmax
    const float* bh   = (const float*)d_in[5];
    const float* Wout = (const float*)d_in[7];
    const float* bout = (const float*)d_in[8];
    float* out = (float*)d_out;

    convert_x_kernel<<<16384, 256>>>(x);
    convert_wqk_kernel<<<128, 256>>>(Wqkv);
    fuse_w_kernel<<<256, 256>>>(Wqkv, bqkv, Wout);
    mma_gemm<false><<<dim3(4, 512), 256>>>(bqkv, nullptr, nullptr);
    attn_kernel<<<4096, 256>>>(Vw, bh);
    mma_gemm<true><<<dim3(2, 512), 256>>>(nullptr, bout, out);
}